// round 1
// baseline (speedup 1.0000x reference)
#include <cuda_runtime.h>
#include <math.h>

#define N_NODES   100000
#define N_EDGES   3200000
#define D         512
#define N_CLASSES 40

// ---------------- scratch (device globals; no allocs allowed) ----------------
__device__ float g_h[(size_t)N_NODES * D];     // current features
__device__ float g_m[(size_t)N_NODES * D];     // aggregated messages
__device__ int   g_indeg[N_NODES];
__device__ int   g_outdeg[N_NODES];
__device__ float g_norm_src[N_NODES];
__device__ float g_norm_dst[N_NODES];
__device__ int   g_rowptr[N_NODES + 1];
__device__ int   g_rowctr[N_NODES];
__device__ int   g_csr_src[N_EDGES];

// ---------------- graph preprocessing ----------------
__global__ void k_zero_ints() {
    int i = blockIdx.x * blockDim.x + threadIdx.x;
    if (i < N_NODES) { g_indeg[i] = 0; g_outdeg[i] = 0; g_rowctr[i] = 0; }
}

__global__ void k_degrees(const int* __restrict__ src, const int* __restrict__ dst) {
    int e = blockIdx.x * blockDim.x + threadIdx.x;
    if (e < N_EDGES) {
        atomicAdd(&g_outdeg[src[e]], 1);
        atomicAdd(&g_indeg[dst[e]], 1);
    }
}

__global__ void k_norms() {
    int i = blockIdx.x * blockDim.x + threadIdx.x;
    if (i < N_NODES) {
        float dо = (float)g_outdeg[i];
        float di = (float)g_indeg[i];
        g_norm_src[i] = rsqrtf(fmaxf(dо, 1.0f));
        g_norm_dst[i] = rsqrtf(fmaxf(di, 1.0f));
    }
}

// single-block inclusive scan of indeg -> rowptr (N=100000, 98 chunks of 1024)
__global__ void k_scan() {
    __shared__ int warp_sums[32];
    __shared__ int s_offset;
    int tid = threadIdx.x;
    int lane = tid & 31, w = tid >> 5;
    if (tid == 0) { s_offset = 0; g_rowptr[0] = 0; }
    __syncthreads();
    for (int base = 0; base < N_NODES; base += 1024) {
        int off = s_offset;
        int i = base + tid;
        int v = (i < N_NODES) ? g_indeg[i] : 0;
        int x = v;
        #pragma unroll
        for (int o = 1; o < 32; o <<= 1) {
            int y = __shfl_up_sync(0xFFFFFFFFu, x, o);
            if (lane >= o) x += y;
        }
        if (lane == 31) warp_sums[w] = x;
        __syncthreads();
        if (w == 0) {
            int y = warp_sums[lane];
            #pragma unroll
            for (int o = 1; o < 32; o <<= 1) {
                int z = __shfl_up_sync(0xFFFFFFFFu, y, o);
                if (lane >= o) y += z;
            }
            warp_sums[lane] = y;
        }
        __syncthreads();
        int incl = x + (w > 0 ? warp_sums[w - 1] : 0) + off;
        if (i < N_NODES) g_rowptr[i + 1] = incl;
        __syncthreads();
        if (tid == 1023) s_offset = incl;
        __syncthreads();
    }
}

__global__ void k_scatter(const int* __restrict__ src, const int* __restrict__ dst) {
    int e = blockIdx.x * blockDim.x + threadIdx.x;
    if (e < N_EDGES) {
        int d = dst[e];
        int pos = g_rowptr[d] + atomicAdd(&g_rowctr[d], 1);
        g_csr_src[pos] = src[e];
    }
}

// ---------------- SpMM: m[v] = norm_dst[v] * sum_{u in N(v)} norm_src[u] * h[u] ----------------
__global__ __launch_bounds__(128) void k_spmm(const float* __restrict__ h,
                                              float* __restrict__ m) {
    int v = blockIdx.x;
    int c = threadIdx.x;          // float4 column index: 128 * 4 = 512
    int beg = g_rowptr[v], end = g_rowptr[v + 1];
    float4 acc = make_float4(0.f, 0.f, 0.f, 0.f);
    int e = beg;
    int u_next = (e < end) ? g_csr_src[e] : 0;
    for (; e < end; e++) {
        int u = u_next;
        u_next = (e + 1 < end) ? g_csr_src[e + 1] : 0;
        float ns = g_norm_src[u];
        float4 x = *(const float4*)(h + (size_t)u * D + c * 4);
        acc.x = fmaf(x.x, ns, acc.x);
        acc.y = fmaf(x.y, ns, acc.y);
        acc.z = fmaf(x.z, ns, acc.z);
        acc.w = fmaf(x.w, ns, acc.w);
    }
    float nd = g_norm_dst[v];
    float4 o = make_float4(acc.x * nd, acc.y * nd, acc.z * nd, acc.w * nd);
    *(float4*)(m + (size_t)v * D + c * 4) = o;
}

// ---------------- GEMM: C[M,512] = A[M,512] @ B[512,512] + bias (opt relu) ----------------
#define BM 128
#define BN 64
#define BK 16

template <bool RELU>
__global__ __launch_bounds__(256) void k_gemm(const float* __restrict__ A,
                                              const float* __restrict__ B,
                                              const float* __restrict__ bias,
                                              float* __restrict__ C, int M) {
    __shared__ float As[BK][BM];
    __shared__ float Bs[BK][BN];
    int tid = threadIdx.x;
    int tx = tid & 15;   // column group: cols tx*4 .. tx*4+3
    int ty = tid >> 4;   // row group:    rows ty*8 .. ty*8+7
    int row0 = blockIdx.y * BM;
    int col0 = blockIdx.x * BN;

    float acc[8][4];
    #pragma unroll
    for (int i = 0; i < 8; i++)
        #pragma unroll
        for (int j = 0; j < 4; j++) acc[i][j] = 0.f;

    for (int k0 = 0; k0 < D; k0 += BK) {
        // A tile: 128 rows x 16 k; 512 float4s, 2 per thread (transposed into As[k][m])
        #pragma unroll
        for (int i = 0; i < 2; i++) {
            int idx = tid + i * 256;
            int mrow = idx >> 2;
            int q = idx & 3;
            int r = row0 + mrow;
            float4 v = make_float4(0.f, 0.f, 0.f, 0.f);
            if (r < M) v = *(const float4*)(A + (size_t)r * D + k0 + q * 4);
            As[q * 4 + 0][mrow] = v.x;
            As[q * 4 + 1][mrow] = v.y;
            As[q * 4 + 2][mrow] = v.z;
            As[q * 4 + 3][mrow] = v.w;
        }
        // B tile: 16 k x 64 n; 256 float4s, 1 per thread
        {
            int k = tid >> 4;
            int nq = tid & 15;
            float4 v = *(const float4*)(B + (size_t)(k0 + k) * D + col0 + nq * 4);
            *(float4*)&Bs[k][nq * 4] = v;
        }
        __syncthreads();
        #pragma unroll
        for (int k = 0; k < BK; k++) {
            float4 b4 = *(float4*)&Bs[k][tx * 4];
            float4 a0 = *(float4*)&As[k][ty * 8];
            float4 a1 = *(float4*)&As[k][ty * 8 + 4];
            float a[8] = {a0.x, a0.y, a0.z, a0.w, a1.x, a1.y, a1.z, a1.w};
            float bb[4] = {b4.x, b4.y, b4.z, b4.w};
            #pragma unroll
            for (int i = 0; i < 8; i++)
                #pragma unroll
                for (int j = 0; j < 4; j++)
                    acc[i][j] = fmaf(a[i], bb[j], acc[i][j]);
        }
        __syncthreads();
    }

    float4 bv = *(const float4*)(bias + col0 + tx * 4);
    float bb[4] = {bv.x, bv.y, bv.z, bv.w};
    #pragma unroll
    for (int i = 0; i < 8; i++) {
        int r = row0 + ty * 8 + i;
        if (r < M) {
            float4 o;
            o.x = acc[i][0] + bb[0];
            o.y = acc[i][1] + bb[1];
            o.z = acc[i][2] + bb[2];
            o.w = acc[i][3] + bb[3];
            if (RELU) {
                o.x = fmaxf(o.x, 0.f); o.y = fmaxf(o.y, 0.f);
                o.z = fmaxf(o.z, 0.f); o.w = fmaxf(o.w, 0.f);
            }
            *(float4*)(C + (size_t)r * D + col0 + tx * 4) = o;
        }
    }
}

// ---------------- final layer: out[M,40] = A[M,512] @ W2[512,40] + b2 ----------------
__global__ __launch_bounds__(256) void k_gemm40(const float* __restrict__ A,
                                                const float* __restrict__ B,
                                                const float* __restrict__ bias,
                                                float* __restrict__ C, int M) {
    int idx = blockIdx.x * blockDim.x + threadIdx.x;
    if (idx >= M * N_CLASSES) return;
    int r = idx / N_CLASSES;
    int c = idx - r * N_CLASSES;
    const float* a = A + (size_t)r * D;
    const float* b = B + c;
    float s = bias[c];
    #pragma unroll 8
    for (int k = 0; k < D; k++) s = fmaf(a[k], b[(size_t)k * N_CLASSES], s);
    C[idx] = s;
}

// ---------------- launch ----------------
extern "C" void kernel_launch(void* const* d_in, const int* in_sizes, int n_in,
                              void* d_out, int out_size) {
    const float* features = (const float*)d_in[0];
    const int*   src      = (const int*)d_in[1];
    const int*   dst      = (const int*)d_in[2];
    const float* W_lin    = (const float*)d_in[3];
    const float* b_lin    = (const float*)d_in[4];
    const float* W0       = (const float*)d_in[5];
    const float* b0       = (const float*)d_in[6];
    const float* W1       = (const float*)d_in[7];
    const float* b1       = (const float*)d_in[8];
    const float* W2       = (const float*)d_in[9];
    const float* b2       = (const float*)d_in[10];
    float* out = (float*)d_out;

    float *h_buf = nullptr, *m_buf = nullptr;
    cudaGetSymbolAddress((void**)&h_buf, g_h);
    cudaGetSymbolAddress((void**)&m_buf, g_m);

    const int NB_N = (N_NODES + 255) / 256;
    const int NB_E = (N_EDGES + 255) / 256;

    // graph build (per call; no state carried across calls)
    k_zero_ints<<<NB_N, 256>>>();
    k_degrees<<<NB_E, 256>>>(src, dst);
    k_norms<<<NB_N, 256>>>();
    k_scan<<<1, 1024>>>();
    k_scatter<<<NB_E, 256>>>(src, dst);

    dim3 ggrid(D / BN, (N_NODES + BM - 1) / BM);

    // h = features @ W_lin + b_lin
    k_gemm<false><<<ggrid, 256>>>(features, W_lin, b_lin, h_buf, N_NODES);

    // layer 0
    k_spmm<<<N_NODES, 128>>>(h_buf, m_buf);
    k_gemm<true><<<ggrid, 256>>>(m_buf, W0, b0, h_buf, N_NODES);

    // layer 1
    k_spmm<<<N_NODES, 128>>>(h_buf, m_buf);
    k_gemm<true><<<ggrid, 256>>>(m_buf, W1, b1, h_buf, N_NODES);

    // layer 2 (no relu, 40 classes) -> d_out
    k_spmm<<<N_NODES, 128>>>(h_buf, m_buf);
    k_gemm40<<<(N_NODES * N_CLASSES + 255) / 256, 256>>>(m_buf, W2, b2, out, N_NODES);
}

// round 2
// speedup vs baseline: 1.2519x; 1.2519x over previous
#include <cuda_runtime.h>
#include <cuda_bf16.h>
#include <math.h>
#include <stdint.h>

#define N_NODES   100000
#define N_EDGES   3200000
#define D         512
#define N_CLASSES 40

// ---------------- scratch (device globals; no allocs allowed) ----------------
__device__ float g_h[(size_t)N_NODES * D];     // current features
__device__ float g_m[(size_t)N_NODES * D];     // aggregated messages
__device__ int   g_indeg[N_NODES];
__device__ int   g_outdeg[N_NODES];
__device__ float g_norm_src[N_NODES];
__device__ float g_norm_dst[N_NODES];
__device__ int   g_rowptr[N_NODES + 1];
__device__ int   g_rowctr[N_NODES];
__device__ int   g_csr_src[N_EDGES];

// ---------------- graph preprocessing ----------------
__global__ void k_zero_ints() {
    int i = blockIdx.x * blockDim.x + threadIdx.x;
    if (i < N_NODES) { g_indeg[i] = 0; g_outdeg[i] = 0; g_rowctr[i] = 0; }
}

__global__ void k_degrees(const int* __restrict__ src, const int* __restrict__ dst) {
    int e = blockIdx.x * blockDim.x + threadIdx.x;
    if (e < N_EDGES) {
        atomicAdd(&g_outdeg[src[e]], 1);
        atomicAdd(&g_indeg[dst[e]], 1);
    }
}

__global__ void k_norms() {
    int i = blockIdx.x * blockDim.x + threadIdx.x;
    if (i < N_NODES) {
        float d_o = (float)g_outdeg[i];
        float d_i = (float)g_indeg[i];
        g_norm_src[i] = rsqrtf(fmaxf(d_o, 1.0f));
        g_norm_dst[i] = rsqrtf(fmaxf(d_i, 1.0f));
    }
}

// single-block inclusive scan of indeg -> rowptr
__global__ void k_scan() {
    __shared__ int warp_sums[32];
    __shared__ int s_offset;
    int tid = threadIdx.x;
    int lane = tid & 31, w = tid >> 5;
    if (tid == 0) { s_offset = 0; g_rowptr[0] = 0; }
    __syncthreads();
    for (int base = 0; base < N_NODES; base += 1024) {
        int off = s_offset;
        int i = base + tid;
        int v = (i < N_NODES) ? g_indeg[i] : 0;
        int x = v;
        #pragma unroll
        for (int o = 1; o < 32; o <<= 1) {
            int y = __shfl_up_sync(0xFFFFFFFFu, x, o);
            if (lane >= o) x += y;
        }
        if (lane == 31) warp_sums[w] = x;
        __syncthreads();
        if (w == 0) {
            int y = warp_sums[lane];
            #pragma unroll
            for (int o = 1; o < 32; o <<= 1) {
                int z = __shfl_up_sync(0xFFFFFFFFu, y, o);
                if (lane >= o) y += z;
            }
            warp_sums[lane] = y;
        }
        __syncthreads();
        int incl = x + (w > 0 ? warp_sums[w - 1] : 0) + off;
        if (i < N_NODES) g_rowptr[i + 1] = incl;
        __syncthreads();
        if (tid == 1023) s_offset = incl;
        __syncthreads();
    }
}

__global__ void k_scatter(const int* __restrict__ src, const int* __restrict__ dst) {
    int e = blockIdx.x * blockDim.x + threadIdx.x;
    if (e < N_EDGES) {
        int d = dst[e];
        int pos = g_rowptr[d] + atomicAdd(&g_rowctr[d], 1);
        g_csr_src[pos] = src[e];
    }
}

// ---------------- SpMM: m[v] = norm_dst[v] * sum_{u in N(v)} norm_src[u] * h[u] ----------------
__global__ __launch_bounds__(128) void k_spmm(const float* __restrict__ h,
                                              float* __restrict__ m) {
    int v = blockIdx.x;
    int c = threadIdx.x;          // float4 column index: 128 * 4 = 512
    int beg = g_rowptr[v], end = g_rowptr[v + 1];
    float4 acc = make_float4(0.f, 0.f, 0.f, 0.f);
    int e = beg;
    int u_next = (e < end) ? g_csr_src[e] : 0;
    for (; e < end; e++) {
        int u = u_next;
        u_next = (e + 1 < end) ? g_csr_src[e + 1] : 0;
        float ns = g_norm_src[u];
        float4 x = *(const float4*)(h + (size_t)u * D + c * 4);
        acc.x = fmaf(x.x, ns, acc.x);
        acc.y = fmaf(x.y, ns, acc.y);
        acc.z = fmaf(x.z, ns, acc.z);
        acc.w = fmaf(x.w, ns, acc.w);
    }
    float nd = g_norm_dst[v];
    float4 o = make_float4(acc.x * nd, acc.y * nd, acc.z * nd, acc.w * nd);
    *(float4*)(m + (size_t)v * D + c * 4) = o;
}

// ---------------- tensor-core GEMM (bf16 split: hi*hi + hi*lo + lo*hi) ----------------
// C[M,512] = A[M,512] @ B[512,512] + bias, optional relu
// Block tile 128x128, BK=16, 8 warps, warp tile 32x64 (2 m-tiles x 8 n-tiles).

#define SA 12   // uint32 row stride in SMEM (conflict-free fragment loads)

__device__ __forceinline__ void split2(float x, float y, uint32_t& hi, uint32_t& lo) {
    __nv_bfloat162 h = __floats2bfloat162_rn(x, y);
    float rx = x - __bfloat162float(h.x);
    float ry = y - __bfloat162float(h.y);
    __nv_bfloat162 l = __floats2bfloat162_rn(rx, ry);
    hi = *reinterpret_cast<uint32_t*>(&h);
    lo = *reinterpret_cast<uint32_t*>(&l);
}

#define MMA_BF16(c, a0, a1, a2, a3, b0, b1)                                    \
    asm volatile("mma.sync.aligned.m16n8k16.row.col.f32.bf16.bf16.f32 "        \
                 "{%0,%1,%2,%3}, {%4,%5,%6,%7}, {%8,%9}, {%0,%1,%2,%3};"       \
                 : "+f"(c[0]), "+f"(c[1]), "+f"(c[2]), "+f"(c[3])              \
                 : "r"(a0), "r"(a1), "r"(a2), "r"(a3), "r"(b0), "r"(b1))

template <bool RELU>
__global__ __launch_bounds__(256, 2) void k_gemm_tc(const float* __restrict__ A,
                                                    const float* __restrict__ B,
                                                    const float* __restrict__ bias,
                                                    float* __restrict__ C, int M) {
    __shared__ uint32_t sA[2][2][128][SA];   // [buf][hi/lo][m][kpair]
    __shared__ uint32_t sB[2][2][128][SA];   // [buf][hi/lo][n][kpair]

    int tid  = threadIdx.x;
    int lane = tid & 31;
    int warp = tid >> 5;
    int wm = (warp & 3) * 32;      // warp row offset in tile
    int wn = (warp >> 2) * 64;     // warp col offset in tile
    int row0 = blockIdx.y * 128;
    int col0 = blockIdx.x * 128;

    float acc[2][8][4];
    #pragma unroll
    for (int i = 0; i < 2; i++)
        #pragma unroll
        for (int j = 0; j < 8; j++)
            #pragma unroll
            for (int k = 0; k < 4; k++) acc[i][j][k] = 0.f;

    // staging registers for next tile
    float4 ra[2], rb0, rb1;
    const int a_m[2] = { tid >> 2, (tid + 256) >> 2 };
    const int a_q    = tid & 3;            // same for both (idx & 3 preserved by +256)
    const int b_kp2  = tid >> 5;           // 0..7  (k = 2*b_kp2)
    const int b_ng   = tid & 31;           // 4-col group

    // ---- load k-slice 0 ----
    {
        #pragma unroll
        for (int i = 0; i < 2; i++) {
            int r = row0 + a_m[i];
            ra[i] = (r < M) ? *(const float4*)(A + (size_t)r * D + a_q * 4)
                            : make_float4(0.f, 0.f, 0.f, 0.f);
        }
        rb0 = *(const float4*)(B + (size_t)(2 * b_kp2) * D + col0 + b_ng * 4);
        rb1 = *(const float4*)(B + (size_t)(2 * b_kp2 + 1) * D + col0 + b_ng * 4);
    }
    // store to smem buf 0
    {
        #pragma unroll
        for (int i = 0; i < 2; i++) {
            uint32_t h0, l0, h1, l1;
            split2(ra[i].x, ra[i].y, h0, l0);
            split2(ra[i].z, ra[i].w, h1, l1);
            sA[0][0][a_m[i]][2 * a_q]     = h0;
            sA[0][0][a_m[i]][2 * a_q + 1] = h1;
            sA[0][1][a_m[i]][2 * a_q]     = l0;
            sA[0][1][a_m[i]][2 * a_q + 1] = l1;
        }
        float u[4] = { rb0.x, rb0.y, rb0.z, rb0.w };
        float w[4] = { rb1.x, rb1.y, rb1.z, rb1.w };
        #pragma unroll
        for (int j = 0; j < 4; j++) {
            uint32_t h, l;
            split2(u[j], w[j], h, l);
            sB[0][0][b_ng * 4 + j][b_kp2] = h;
            sB[0][1][b_ng * 4 + j][b_kp2] = l;
        }
    }
    __syncthreads();

    const int NK = D / 16;   // 32
    for (int ks = 0; ks < NK; ks++) {
        int buf = ks & 1;
        // prefetch next slice into regs
        if (ks + 1 < NK) {
            int k0 = (ks + 1) * 16;
            #pragma unroll
            for (int i = 0; i < 2; i++) {
                int r = row0 + a_m[i];
                ra[i] = (r < M) ? *(const float4*)(A + (size_t)r * D + k0 + a_q * 4)
                                : make_float4(0.f, 0.f, 0.f, 0.f);
            }
            rb0 = *(const float4*)(B + (size_t)(k0 + 2 * b_kp2) * D + col0 + b_ng * 4);
            rb1 = *(const float4*)(B + (size_t)(k0 + 2 * b_kp2 + 1) * D + col0 + b_ng * 4);
        }
        // compute on current buffer
        int kp = lane & 3;
        int fr = lane >> 2;
        #pragma unroll
        for (int mt = 0; mt < 2; mt++) {
            int r = wm + mt * 16 + fr;
            uint32_t ah0 = sA[buf][0][r][kp];
            uint32_t ah1 = sA[buf][0][r + 8][kp];
            uint32_t ah2 = sA[buf][0][r][kp + 4];
            uint32_t ah3 = sA[buf][0][r + 8][kp + 4];
            uint32_t al0 = sA[buf][1][r][kp];
            uint32_t al1 = sA[buf][1][r + 8][kp];
            uint32_t al2 = sA[buf][1][r][kp + 4];
            uint32_t al3 = sA[buf][1][r + 8][kp + 4];
            #pragma unroll
            for (int nt = 0; nt < 8; nt++) {
                int n = wn + nt * 8 + fr;
                uint32_t bh0 = sB[buf][0][n][kp];
                uint32_t bh1 = sB[buf][0][n][kp + 4];
                uint32_t bl0 = sB[buf][1][n][kp];
                uint32_t bl1 = sB[buf][1][n][kp + 4];
                MMA_BF16(acc[mt][nt], ah0, ah1, ah2, ah3, bh0, bh1);
                MMA_BF16(acc[mt][nt], ah0, ah1, ah2, ah3, bl0, bl1);
                MMA_BF16(acc[mt][nt], al0, al1, al2, al3, bh0, bh1);
            }
        }
        // stage next slice into the other buffer
        if (ks + 1 < NK) {
            int nb = buf ^ 1;
            #pragma unroll
            for (int i = 0; i < 2; i++) {
                uint32_t h0, l0, h1, l1;
                split2(ra[i].x, ra[i].y, h0, l0);
                split2(ra[i].z, ra[i].w, h1, l1);
                sA[nb][0][a_m[i]][2 * a_q]     = h0;
                sA[nb][0][a_m[i]][2 * a_q + 1] = h1;
                sA[nb][1][a_m[i]][2 * a_q]     = l0;
                sA[nb][1][a_m[i]][2 * a_q + 1] = l1;
            }
            float u[4] = { rb0.x, rb0.y, rb0.z, rb0.w };
            float w[4] = { rb1.x, rb1.y, rb1.z, rb1.w };
            #pragma unroll
            for (int j = 0; j < 4; j++) {
                uint32_t h, l;
                split2(u[j], w[j], h, l);
                sB[nb][0][b_ng * 4 + j][b_kp2] = h;
                sB[nb][1][b_ng * 4 + j][b_kp2] = l;
            }
            __syncthreads();
        }
    }

    // ---- epilogue: bias (+relu), store ----
    int fr = lane >> 2;
    int fc = (lane & 3) * 2;
    #pragma unroll
    for (int mt = 0; mt < 2; mt++) {
        #pragma unroll
        for (int nt = 0; nt < 8; nt++) {
            int cb = col0 + wn + nt * 8 + fc;
            float bb0 = bias[cb], bb1 = bias[cb + 1];
            int r = row0 + wm + mt * 16 + fr;
            float v0 = acc[mt][nt][0] + bb0;
            float v1 = acc[mt][nt][1] + bb1;
            float v2 = acc[mt][nt][2] + bb0;
            float v3 = acc[mt][nt][3] + bb1;
            if (RELU) {
                v0 = fmaxf(v0, 0.f); v1 = fmaxf(v1, 0.f);
                v2 = fmaxf(v2, 0.f); v3 = fmaxf(v3, 0.f);
            }
            if (r < M)     *(float2*)(C + (size_t)r * D + cb)       = make_float2(v0, v1);
            if (r + 8 < M) *(float2*)(C + (size_t)(r + 8) * D + cb) = make_float2(v2, v3);
        }
    }
}

// ---------------- final layer: out[M,40] = A[M,512] @ W2[512,40] + b2 ----------------
__global__ __launch_bounds__(256) void k_gemm40(const float* __restrict__ A,
                                                const float* __restrict__ B,
                                                const float* __restrict__ bias,
                                                float* __restrict__ C, int M) {
    int idx = blockIdx.x * blockDim.x + threadIdx.x;
    if (idx >= M * N_CLASSES) return;
    int r = idx / N_CLASSES;
    int c = idx - r * N_CLASSES;
    const float* a = A + (size_t)r * D;
    const float* b = B + c;
    float s = bias[c];
    #pragma unroll 8
    for (int k = 0; k < D; k++) s = fmaf(a[k], b[(size_t)k * N_CLASSES], s);
    C[idx] = s;
}

// ---------------- launch ----------------
extern "C" void kernel_launch(void* const* d_in, const int* in_sizes, int n_in,
                              void* d_out, int out_size) {
    const float* features = (const float*)d_in[0];
    const int*   src      = (const int*)d_in[1];
    const int*   dst      = (const int*)d_in[2];
    const float* W_lin    = (const float*)d_in[3];
    const float* b_lin    = (const float*)d_in[4];
    const float* W0       = (const float*)d_in[5];
    const float* b0       = (const float*)d_in[6];
    const float* W1       = (const float*)d_in[7];
    const float* b1       = (const float*)d_in[8];
    const float* W2       = (const float*)d_in[9];
    const float* b2       = (const float*)d_in[10];
    float* out = (float*)d_out;

    float *h_buf = nullptr, *m_buf = nullptr;
    cudaGetSymbolAddress((void**)&h_buf, g_h);
    cudaGetSymbolAddress((void**)&m_buf, g_m);

    const int NB_N = (N_NODES + 255) / 256;
    const int NB_E = (N_EDGES + 255) / 256;

    // graph build (per call; no state carried across calls)
    k_zero_ints<<<NB_N, 256>>>();
    k_degrees<<<NB_E, 256>>>(src, dst);
    k_norms<<<NB_N, 256>>>();
    k_scan<<<1, 1024>>>();
    k_scatter<<<NB_E, 256>>>(src, dst);

    dim3 ggrid(D / 128, (N_NODES + 127) / 128);

    // h = features @ W_lin + b_lin
    k_gemm_tc<false><<<ggrid, 256>>>(features, W_lin, b_lin, h_buf, N_NODES);

    // layer 0
    k_spmm<<<N_NODES, 128>>>(h_buf, m_buf);
    k_gemm_tc<true><<<ggrid, 256>>>(m_buf, W0, b0, h_buf, N_NODES);

    // layer 1
    k_spmm<<<N_NODES, 128>>>(h_buf, m_buf);
    k_gemm_tc<true><<<ggrid, 256>>>(m_buf, W1, b1, h_buf, N_NODES);

    // layer 2 (no relu, 40 classes) -> d_out
    k_spmm<<<N_NODES, 128>>>(h_buf, m_buf);
    k_gemm40<<<(N_NODES * N_CLASSES + 255) / 256, 256>>>(m_buf, W2, b2, out, N_NODES);
}

// round 3
// speedup vs baseline: 1.6768x; 1.3393x over previous
#include <cuda_runtime.h>
#include <cuda_bf16.h>
#include <math.h>
#include <stdint.h>

#define N_NODES   100000
#define N_EDGES   3200000
#define D         512
#define N_CLASSES 40

// ---------------- scratch (device globals; no allocs allowed) ----------------
__device__ float g_h[(size_t)N_NODES * D];     // current features
__device__ float g_z[(size_t)N_NODES * D];     // GEMM output / SpMM input
__device__ int   g_indeg[N_NODES];
__device__ int   g_outdeg[N_NODES];
__device__ float g_norm_src[N_NODES];
__device__ float g_norm_dst[N_NODES];
__device__ int   g_rowptr[N_NODES + 1];
__device__ int   g_rowctr[N_NODES];
__device__ int   g_csr_src[N_EDGES];

// ---------------- graph preprocessing ----------------
__global__ void k_zero_ints() {
    int i = blockIdx.x * blockDim.x + threadIdx.x;
    if (i < N_NODES) { g_indeg[i] = 0; g_outdeg[i] = 0; g_rowctr[i] = 0; }
}

__global__ void k_degrees(const int* __restrict__ src, const int* __restrict__ dst) {
    int e = blockIdx.x * blockDim.x + threadIdx.x;
    if (e < N_EDGES) {
        atomicAdd(&g_outdeg[src[e]], 1);
        atomicAdd(&g_indeg[dst[e]], 1);
    }
}

__global__ void k_norms() {
    int i = blockIdx.x * blockDim.x + threadIdx.x;
    if (i < N_NODES) {
        float d_o = (float)g_outdeg[i];
        float d_i = (float)g_indeg[i];
        g_norm_src[i] = rsqrtf(fmaxf(d_o, 1.0f));
        g_norm_dst[i] = rsqrtf(fmaxf(d_i, 1.0f));
    }
}

// single-block inclusive scan of indeg -> rowptr
__global__ void k_scan() {
    __shared__ int warp_sums[32];
    __shared__ int s_offset;
    int tid = threadIdx.x;
    int lane = tid & 31, w = tid >> 5;
    if (tid == 0) { s_offset = 0; g_rowptr[0] = 0; }
    __syncthreads();
    for (int base = 0; base < N_NODES; base += 1024) {
        int off = s_offset;
        int i = base + tid;
        int v = (i < N_NODES) ? g_indeg[i] : 0;
        int x = v;
        #pragma unroll
        for (int o = 1; o < 32; o <<= 1) {
            int y = __shfl_up_sync(0xFFFFFFFFu, x, o);
            if (lane >= o) x += y;
        }
        if (lane == 31) warp_sums[w] = x;
        __syncthreads();
        if (w == 0) {
            int y = warp_sums[lane];
            #pragma unroll
            for (int o = 1; o < 32; o <<= 1) {
                int z = __shfl_up_sync(0xFFFFFFFFu, y, o);
                if (lane >= o) y += z;
            }
            warp_sums[lane] = y;
        }
        __syncthreads();
        int incl = x + (w > 0 ? warp_sums[w - 1] : 0) + off;
        if (i < N_NODES) g_rowptr[i + 1] = incl;
        __syncthreads();
        if (tid == 1023) s_offset = incl;
        __syncthreads();
    }
}

__global__ void k_scatter(const int* __restrict__ src, const int* __restrict__ dst) {
    int e = blockIdx.x * blockDim.x + threadIdx.x;
    if (e < N_EDGES) {
        int d = dst[e];
        int pos = g_rowptr[d] + atomicAdd(&g_rowctr[d], 1);
        g_csr_src[pos] = src[e];
    }
}

// ---------------- SpMM (column-chunked, pure row-sum): ----------------
// out[v, cols] = relu?( norm_dst[v] * sum_u z[u, cols] + bias[cols] )
// One warp per node; chunk covers 128 floats (32 float4 lanes).
template <bool RELU>
__global__ __launch_bounds__(128) void k_spmm_chunk(const float* __restrict__ z,
                                                    const float* __restrict__ bias,
                                                    float* __restrict__ out,
                                                    int chunk) {
    int v = blockIdx.x * 4 + (threadIdx.x >> 5);
    if (v >= N_NODES) return;
    int lane = threadIdx.x & 31;
    int coff = chunk * 128 + lane * 4;

    int beg = g_rowptr[v], end = g_rowptr[v + 1];
    float4 acc0 = make_float4(0.f, 0.f, 0.f, 0.f);
    float4 acc1 = make_float4(0.f, 0.f, 0.f, 0.f);
    int e = beg;
    for (; e + 1 < end; e += 2) {
        int u0 = g_csr_src[e];
        int u1 = g_csr_src[e + 1];
        float4 x0 = *(const float4*)(z + (size_t)u0 * D + coff);
        float4 x1 = *(const float4*)(z + (size_t)u1 * D + coff);
        acc0.x += x0.x; acc0.y += x0.y; acc0.z += x0.z; acc0.w += x0.w;
        acc1.x += x1.x; acc1.y += x1.y; acc1.z += x1.z; acc1.w += x1.w;
    }
    if (e < end) {
        int u0 = g_csr_src[e];
        float4 x0 = *(const float4*)(z + (size_t)u0 * D + coff);
        acc0.x += x0.x; acc0.y += x0.y; acc0.z += x0.z; acc0.w += x0.w;
    }
    float nd = g_norm_dst[v];
    float4 bv = *(const float4*)(bias + coff);
    float4 o;
    o.x = fmaf(acc0.x + acc1.x, nd, bv.x);
    o.y = fmaf(acc0.y + acc1.y, nd, bv.y);
    o.z = fmaf(acc0.z + acc1.z, nd, bv.z);
    o.w = fmaf(acc0.w + acc1.w, nd, bv.w);
    if (RELU) {
        o.x = fmaxf(o.x, 0.f); o.y = fmaxf(o.y, 0.f);
        o.z = fmaxf(o.z, 0.f); o.w = fmaxf(o.w, 0.f);
    }
    *(float4*)(out + (size_t)v * D + coff) = o;
}

// ---------------- SpMM for 40-wide final layer (z40 is L2-resident, 16MB) ----------------
// out[v, 0:40] = norm_dst[v] * sum_u z40[u, 0:40] + b2   (no relu)
__global__ __launch_bounds__(256) void k_spmm40(const float* __restrict__ z40,
                                                const float* __restrict__ bias,
                                                float* __restrict__ out) {
    int v = blockIdx.x * 8 + (threadIdx.x >> 5);
    if (v >= N_NODES) return;
    int lane = threadIdx.x & 31;
    if (lane >= 20) return;                 // 20 lanes x float2 = 40 cols
    int c = lane * 2;

    int beg = g_rowptr[v], end = g_rowptr[v + 1];
    float2 acc0 = make_float2(0.f, 0.f);
    float2 acc1 = make_float2(0.f, 0.f);
    int e = beg;
    for (; e + 1 < end; e += 2) {
        int u0 = g_csr_src[e];
        int u1 = g_csr_src[e + 1];
        float2 x0 = *(const float2*)(z40 + (size_t)u0 * N_CLASSES + c);
        float2 x1 = *(const float2*)(z40 + (size_t)u1 * N_CLASSES + c);
        acc0.x += x0.x; acc0.y += x0.y;
        acc1.x += x1.x; acc1.y += x1.y;
    }
    if (e < end) {
        int u0 = g_csr_src[e];
        float2 x0 = *(const float2*)(z40 + (size_t)u0 * N_CLASSES + c);
        acc0.x += x0.x; acc0.y += x0.y;
    }
    float nd = g_norm_dst[v];
    float2 o;
    o.x = fmaf(acc0.x + acc1.x, nd, bias[c]);
    o.y = fmaf(acc0.y + acc1.y, nd, bias[c + 1]);
    *(float2*)(out + (size_t)v * N_CLASSES + c) = o;
}

// ---------------- tensor-core GEMM (bf16 split: hi*hi + hi*lo + lo*hi) ----------------
// C[M,512] = (A[M,512] @ B[512,512] [+ bias]) [* row_scale[r]]
#define SA 12

__device__ __forceinline__ void split2(float x, float y, uint32_t& hi, uint32_t& lo) {
    __nv_bfloat162 h = __floats2bfloat162_rn(x, y);
    float rx = x - __bfloat162float(h.x);
    float ry = y - __bfloat162float(h.y);
    __nv_bfloat162 l = __floats2bfloat162_rn(rx, ry);
    hi = *reinterpret_cast<uint32_t*>(&h);
    lo = *reinterpret_cast<uint32_t*>(&l);
}

#define MMA_BF16(c, a0, a1, a2, a3, b0, b1)                                    \
    asm volatile("mma.sync.aligned.m16n8k16.row.col.f32.bf16.bf16.f32 "        \
                 "{%0,%1,%2,%3}, {%4,%5,%6,%7}, {%8,%9}, {%0,%1,%2,%3};"       \
                 : "+f"(c[0]), "+f"(c[1]), "+f"(c[2]), "+f"(c[3])              \
                 : "r"(a0), "r"(a1), "r"(a2), "r"(a3), "r"(b0), "r"(b1))

template <bool ADD_BIAS, bool SCALE_ROW>
__global__ __launch_bounds__(256, 2) void k_gemm_tc(const float* __restrict__ A,
                                                    const float* __restrict__ B,
                                                    const float* __restrict__ bias,
                                                    const float* __restrict__ row_scale,
                                                    float* __restrict__ C, int M) {
    __shared__ uint32_t sA[2][2][128][SA];
    __shared__ uint32_t sB[2][2][128][SA];

    int tid  = threadIdx.x;
    int lane = tid & 31;
    int warp = tid >> 5;
    int wm = (warp & 3) * 32;
    int wn = (warp >> 2) * 64;
    int row0 = blockIdx.y * 128;
    int col0 = blockIdx.x * 128;

    float acc[2][8][4];
    #pragma unroll
    for (int i = 0; i < 2; i++)
        #pragma unroll
        for (int j = 0; j < 8; j++)
            #pragma unroll
            for (int k = 0; k < 4; k++) acc[i][j][k] = 0.f;

    float4 ra[2], rb0, rb1;
    const int a_m[2] = { tid >> 2, (tid + 256) >> 2 };
    const int a_q    = tid & 3;
    const int b_kp2  = tid >> 5;
    const int b_ng   = tid & 31;

    {
        #pragma unroll
        for (int i = 0; i < 2; i++) {
            int r = row0 + a_m[i];
            ra[i] = (r < M) ? *(const float4*)(A + (size_t)r * D + a_q * 4)
                            : make_float4(0.f, 0.f, 0.f, 0.f);
        }
        rb0 = *(const float4*)(B + (size_t)(2 * b_kp2) * D + col0 + b_ng * 4);
        rb1 = *(const float4*)(B + (size_t)(2 * b_kp2 + 1) * D + col0 + b_ng * 4);
    }
    {
        #pragma unroll
        for (int i = 0; i < 2; i++) {
            uint32_t h0, l0, h1, l1;
            split2(ra[i].x, ra[i].y, h0, l0);
            split2(ra[i].z, ra[i].w, h1, l1);
            sA[0][0][a_m[i]][2 * a_q]     = h0;
            sA[0][0][a_m[i]][2 * a_q + 1] = h1;
            sA[0][1][a_m[i]][2 * a_q]     = l0;
            sA[0][1][a_m[i]][2 * a_q + 1] = l1;
        }
        float u[4] = { rb0.x, rb0.y, rb0.z, rb0.w };
        float w[4] = { rb1.x, rb1.y, rb1.z, rb1.w };
        #pragma unroll
        for (int j = 0; j < 4; j++) {
            uint32_t h, l;
            split2(u[j], w[j], h, l);
            sB[0][0][b_ng * 4 + j][b_kp2] = h;
            sB[0][1][b_ng * 4 + j][b_kp2] = l;
        }
    }
    __syncthreads();

    const int NK = D / 16;
    for (int ks = 0; ks < NK; ks++) {
        int buf = ks & 1;
        if (ks + 1 < NK) {
            int k0 = (ks + 1) * 16;
            #pragma unroll
            for (int i = 0; i < 2; i++) {
                int r = row0 + a_m[i];
                ra[i] = (r < M) ? *(const float4*)(A + (size_t)r * D + k0 + a_q * 4)
                                : make_float4(0.f, 0.f, 0.f, 0.f);
            }
            rb0 = *(const float4*)(B + (size_t)(k0 + 2 * b_kp2) * D + col0 + b_ng * 4);
            rb1 = *(const float4*)(B + (size_t)(k0 + 2 * b_kp2 + 1) * D + col0 + b_ng * 4);
        }
        int kp = lane & 3;
        int fr = lane >> 2;
        #pragma unroll
        for (int mt = 0; mt < 2; mt++) {
            int r = wm + mt * 16 + fr;
            uint32_t ah0 = sA[buf][0][r][kp];
            uint32_t ah1 = sA[buf][0][r + 8][kp];
            uint32_t ah2 = sA[buf][0][r][kp + 4];
            uint32_t ah3 = sA[buf][0][r + 8][kp + 4];
            uint32_t al0 = sA[buf][1][r][kp];
            uint32_t al1 = sA[buf][1][r + 8][kp];
            uint32_t al2 = sA[buf][1][r][kp + 4];
            uint32_t al3 = sA[buf][1][r + 8][kp + 4];
            #pragma unroll
            for (int nt = 0; nt < 8; nt++) {
                int n = wn + nt * 8 + fr;
                uint32_t bh0 = sB[buf][0][n][kp];
                uint32_t bh1 = sB[buf][0][n][kp + 4];
                uint32_t bl0 = sB[buf][1][n][kp];
                uint32_t bl1 = sB[buf][1][n][kp + 4];
                MMA_BF16(acc[mt][nt], ah0, ah1, ah2, ah3, bh0, bh1);
                MMA_BF16(acc[mt][nt], ah0, ah1, ah2, ah3, bl0, bl1);
                MMA_BF16(acc[mt][nt], al0, al1, al2, al3, bh0, bh1);
            }
        }
        if (ks + 1 < NK) {
            int nb = buf ^ 1;
            #pragma unroll
            for (int i = 0; i < 2; i++) {
                uint32_t h0, l0, h1, l1;
                split2(ra[i].x, ra[i].y, h0, l0);
                split2(ra[i].z, ra[i].w, h1, l1);
                sA[nb][0][a_m[i]][2 * a_q]     = h0;
                sA[nb][0][a_m[i]][2 * a_q + 1] = h1;
                sA[nb][1][a_m[i]][2 * a_q]     = l0;
                sA[nb][1][a_m[i]][2 * a_q + 1] = l1;
            }
            float u[4] = { rb0.x, rb0.y, rb0.z, rb0.w };
            float w[4] = { rb1.x, rb1.y, rb1.z, rb1.w };
            #pragma unroll
            for (int j = 0; j < 4; j++) {
                uint32_t h, l;
                split2(u[j], w[j], h, l);
                sB[nb][0][b_ng * 4 + j][b_kp2] = h;
                sB[nb][1][b_ng * 4 + j][b_kp2] = l;
            }
            __syncthreads();
        }
    }

    int fr = lane >> 2;
    int fc = (lane & 3) * 2;
    #pragma unroll
    for (int mt = 0; mt < 2; mt++) {
        int r = row0 + wm + mt * 16 + fr;
        float s0 = 1.f, s1 = 1.f;
        if (SCALE_ROW) {
            if (r < M)     s0 = row_scale[r];
            if (r + 8 < M) s1 = row_scale[r + 8];
        }
        #pragma unroll
        for (int nt = 0; nt < 8; nt++) {
            int cb = col0 + wn + nt * 8 + fc;
            float bb0 = 0.f, bb1 = 0.f;
            if (ADD_BIAS) { bb0 = bias[cb]; bb1 = bias[cb + 1]; }
            float v0 = (acc[mt][nt][0] + bb0) * s0;
            float v1 = (acc[mt][nt][1] + bb1) * s0;
            float v2 = (acc[mt][nt][2] + bb0) * s1;
            float v3 = (acc[mt][nt][3] + bb1) * s1;
            if (r < M)     *(float2*)(C + (size_t)r * D + cb)       = make_float2(v0, v1);
            if (r + 8 < M) *(float2*)(C + (size_t)(r + 8) * D + cb) = make_float2(v2, v3);
        }
    }
}

// ---------------- final GEMM: z40[M,40] = (A[M,512] @ W2[512,40]) * norm_src[r] ----------------
__global__ __launch_bounds__(256) void k_gemm40(const float* __restrict__ A,
                                                const float* __restrict__ B,
                                                const float* __restrict__ row_scale,
                                                float* __restrict__ C, int M) {
    int idx = blockIdx.x * blockDim.x + threadIdx.x;
    if (idx >= M * N_CLASSES) return;
    int r = idx / N_CLASSES;
    int c = idx - r * N_CLASSES;
    const float* a = A + (size_t)r * D;
    const float* b = B + c;
    float s = 0.f;
    #pragma unroll 8
    for (int k = 0; k < D; k++) s = fmaf(a[k], b[(size_t)k * N_CLASSES], s);
    C[idx] = s * row_scale[r];
}

// ---------------- launch ----------------
extern "C" void kernel_launch(void* const* d_in, const int* in_sizes, int n_in,
                              void* d_out, int out_size) {
    const float* features = (const float*)d_in[0];
    const int*   src      = (const int*)d_in[1];
    const int*   dst      = (const int*)d_in[2];
    const float* W_lin    = (const float*)d_in[3];
    const float* b_lin    = (const float*)d_in[4];
    const float* W0       = (const float*)d_in[5];
    const float* b0       = (const float*)d_in[6];
    const float* W1       = (const float*)d_in[7];
    const float* b1       = (const float*)d_in[8];
    const float* W2       = (const float*)d_in[9];
    const float* b2       = (const float*)d_in[10];
    float* out = (float*)d_out;

    float *h_buf = nullptr, *z_buf = nullptr, *ns_buf = nullptr;
    cudaGetSymbolAddress((void**)&h_buf, g_h);
    cudaGetSymbolAddress((void**)&z_buf, g_z);
    cudaGetSymbolAddress((void**)&ns_buf, g_norm_src);

    const int NB_N = (N_NODES + 255) / 256;
    const int NB_E = (N_EDGES + 255) / 256;

    // graph build
    k_zero_ints<<<NB_N, 256>>>();
    k_degrees<<<NB_E, 256>>>(src, dst);
    k_norms<<<NB_N, 256>>>();
    k_scan<<<1, 1024>>>();
    k_scatter<<<NB_E, 256>>>(src, dst);

    dim3 ggrid(D / 128, (N_NODES + 127) / 128);
    const int spmm_blocks = (N_NODES + 3) / 4;

    // h = features @ W_lin + b_lin
    k_gemm_tc<true, false><<<ggrid, 256>>>(features, W_lin, b_lin, nullptr, h_buf, N_NODES);

    // layer 0: z = (h @ W0) * norm_src ; h = relu(S_sum(z) * norm_dst + b0)
    k_gemm_tc<false, true><<<ggrid, 256>>>(h_buf, W0, nullptr, ns_buf, z_buf, N_NODES);
    for (int c = 0; c < 4; c++)
        k_spmm_chunk<true><<<spmm_blocks, 128>>>(z_buf, b0, h_buf, c);

    // layer 1
    k_gemm_tc<false, true><<<ggrid, 256>>>(h_buf, W1, nullptr, ns_buf, z_buf, N_NODES);
    for (int c = 0; c < 4; c++)
        k_spmm_chunk<true><<<spmm_blocks, 128>>>(z_buf, b1, h_buf, c);

    // layer 2: z40 = (h @ W2) * norm_src ; out = S_sum(z40) * norm_dst + b2
    k_gemm40<<<(N_NODES * N_CLASSES + 255) / 256, 256>>>(h_buf, W2, ns_buf, z_buf, N_NODES);
    k_spmm40<<<(N_NODES + 7) / 8, 256>>>(z_buf, b2, out);
}

// round 4
// speedup vs baseline: 2.7004x; 1.6105x over previous
#include <cuda_runtime.h>
#include <cuda_bf16.h>
#include <cuda_fp16.h>
#include <math.h>
#include <stdint.h>

#define N_NODES   100000
#define N_EDGES   3200000
#define D         512
#define N_CLASSES 40
#define NSCAN_BLK 98

// ---------------- scratch (device globals; no allocs allowed) ----------------
__device__ __nv_bfloat16 g_fhi[(size_t)N_NODES * D];   // A buffer 0 (hi)
__device__ __nv_bfloat16 g_flo[(size_t)N_NODES * D];   // A buffer 0 (lo)
__device__ __nv_bfloat16 g_hhi[(size_t)N_NODES * D];   // A buffer 1 (hi)
__device__ __nv_bfloat16 g_hlo[(size_t)N_NODES * D];   // A buffer 1 (lo)
__device__ __half        g_z16[(size_t)N_NODES * D];   // GEMM out / SpMM in
__device__ float         g_z40[(size_t)N_NODES * N_CLASSES];
__device__ __nv_bfloat16 g_wl_hi[D * D],  g_wl_lo[D * D];     // W_lin^T
__device__ __nv_bfloat16 g_w0_hi[D * D],  g_w0_lo[D * D];     // W0^T
__device__ __nv_bfloat16 g_w1_hi[D * D],  g_w1_lo[D * D];     // W1^T
__device__ __nv_bfloat16 g_w2_hi[128 * D], g_w2_lo[128 * D];  // W2^T padded to 128 rows
__device__ int   g_indeg[N_NODES];
__device__ int   g_outdeg[N_NODES];
__device__ float g_norm_src[N_NODES];
__device__ float g_norm_dst[N_NODES];
__device__ int   g_rowptr[N_NODES + 1];
__device__ int   g_rowctr[N_NODES];
__device__ int   g_csr_src[N_EDGES];
__device__ int   g_blksum[NSCAN_BLK];
__device__ int   g_blkoff[NSCAN_BLK];

// ---------------- helpers ----------------
__device__ __forceinline__ void split2(float x, float y, uint32_t& hi, uint32_t& lo) {
    __nv_bfloat162 h = __floats2bfloat162_rn(x, y);
    float rx = x - __bfloat162float(h.x);
    float ry = y - __bfloat162float(h.y);
    __nv_bfloat162 l = __floats2bfloat162_rn(rx, ry);
    hi = *reinterpret_cast<uint32_t*>(&h);
    lo = *reinterpret_cast<uint32_t*>(&l);
}

__device__ __forceinline__ void cp16(uint32_t dst_smem, const void* src, bool valid) {
    asm volatile("cp.async.cg.shared.global [%0], [%1], 16, %2;"
                 :: "r"(dst_smem), "l"(src), "r"(valid ? 16 : 0));
}
__device__ __forceinline__ void cp_commit() {
    asm volatile("cp.async.commit_group;");
}
template <int N>
__device__ __forceinline__ void cp_wait() {
    asm volatile("cp.async.wait_group %0;" :: "n"(N));
}

#define MMA_BF16(c, a0, a1, a2, a3, b0, b1)                                    \
    asm volatile("mma.sync.aligned.m16n8k16.row.col.f32.bf16.bf16.f32 "        \
                 "{%0,%1,%2,%3}, {%4,%5,%6,%7}, {%8,%9}, {%0,%1,%2,%3};"       \
                 : "+f"(c[0]), "+f"(c[1]), "+f"(c[2]), "+f"(c[3])              \
                 : "r"(a0), "r"(a1), "r"(a2), "r"(a3), "r"(b0), "r"(b1))

// ---------------- graph preprocessing ----------------
__global__ void k_zero_ints() {
    int i = blockIdx.x * blockDim.x + threadIdx.x;
    if (i < N_NODES) { g_indeg[i] = 0; g_outdeg[i] = 0; g_rowctr[i] = 0; }
}

__global__ void k_degrees(const int* __restrict__ src, const int* __restrict__ dst) {
    int e = blockIdx.x * blockDim.x + threadIdx.x;
    if (e < N_EDGES) {
        atomicAdd(&g_outdeg[src[e]], 1);
        atomicAdd(&g_indeg[dst[e]], 1);
    }
}

__global__ void k_norms() {
    int i = blockIdx.x * blockDim.x + threadIdx.x;
    if (i < N_NODES) {
        g_norm_src[i] = rsqrtf(fmaxf((float)g_outdeg[i], 1.0f));
        g_norm_dst[i] = rsqrtf(fmaxf((float)g_indeg[i], 1.0f));
    }
}

__global__ void k_scan1() {
    __shared__ int ws[32];
    int tid = threadIdx.x, lane = tid & 31, w = tid >> 5;
    int i = blockIdx.x * 1024 + tid;
    int v = (i < N_NODES) ? g_indeg[i] : 0;
    int x = v;
    #pragma unroll
    for (int o = 1; o < 32; o <<= 1) {
        int y = __shfl_up_sync(0xFFFFFFFFu, x, o);
        if (lane >= o) x += y;
    }
    if (lane == 31) ws[w] = x;
    __syncthreads();
    if (w == 0) {
        int y = ws[lane];
        #pragma unroll
        for (int o = 1; o < 32; o <<= 1) {
            int z = __shfl_up_sync(0xFFFFFFFFu, y, o);
            if (lane >= o) y += z;
        }
        ws[lane] = y;
    }
    __syncthreads();
    int incl = x + (w > 0 ? ws[w - 1] : 0);
    if (i < N_NODES) g_rowptr[i + 1] = incl;
    if (tid == 1023) g_blksum[blockIdx.x] = incl;
}

__global__ void k_scan2() {
    __shared__ int ws[4];
    int tid = threadIdx.x, lane = tid & 31, w = tid >> 5;
    int v = (tid < NSCAN_BLK) ? g_blksum[tid] : 0;
    int x = v;
    #pragma unroll
    for (int o = 1; o < 32; o <<= 1) {
        int y = __shfl_up_sync(0xFFFFFFFFu, x, o);
        if (lane >= o) x += y;
    }
    if (lane == 31) ws[w] = x;
    __syncthreads();
    if (tid == 0) {
        int s = 0;
        #pragma unroll
        for (int j = 0; j < 4; j++) { int t = ws[j]; ws[j] = s; s += t; }
    }
    __syncthreads();
    int excl = x - v + ws[w];
    if (tid < NSCAN_BLK) g_blkoff[tid] = excl;
}

__global__ void k_scan3() {
    int i = blockIdx.x * 1024 + threadIdx.x;
    if (i < N_NODES) g_rowptr[i + 1] += g_blkoff[blockIdx.x];
    if (i == 0) g_rowptr[0] = 0;
}

__global__ void k_scatter(const int* __restrict__ src, const int* __restrict__ dst) {
    int e = blockIdx.x * blockDim.x + threadIdx.x;
    if (e < N_EDGES) {
        int d = dst[e];
        int pos = g_rowptr[d] + atomicAdd(&g_rowctr[d], 1);
        g_csr_src[pos] = src[e];
    }
}

// ---------------- split passes ----------------
__global__ void k_split_feat(const float* __restrict__ f) {
    size_t i = ((size_t)blockIdx.x * blockDim.x + threadIdx.x) * 8;
    float4 a = *(const float4*)(f + i);
    float4 b = *(const float4*)(f + i + 4);
    uint32_t h[4], l[4];
    split2(a.x, a.y, h[0], l[0]);
    split2(a.z, a.w, h[1], l[1]);
    split2(b.x, b.y, h[2], l[2]);
    split2(b.z, b.w, h[3], l[3]);
    *(uint4*)(g_fhi + i) = make_uint4(h[0], h[1], h[2], h[3]);
    *(uint4*)(g_flo + i) = make_uint4(l[0], l[1], l[2], l[3]);
}

// W [k][n] fp32 -> W^T [n][k] bf16 hi/lo
__global__ void k_split_w(const float* __restrict__ W,
                          __nv_bfloat16* __restrict__ hi,
                          __nv_bfloat16* __restrict__ lo) {
    int idx = blockIdx.x * blockDim.x + threadIdx.x;   // 512*512
    int k = idx >> 9, n = idx & 511;
    float v = W[k * 512 + n];
    __nv_bfloat16 h = __float2bfloat16(v);
    float r = v - __bfloat162float(h);
    hi[n * 512 + k] = h;
    lo[n * 512 + k] = __float2bfloat16(r);
}

// W2 [k][40] fp32 -> padded [128][512] bf16 hi/lo
__global__ void k_split_w2(const float* __restrict__ W2) {
    int idx = blockIdx.x * blockDim.x + threadIdx.x;   // 128*512
    int n = idx >> 9, k = idx & 511;
    float v = (n < N_CLASSES) ? W2[k * N_CLASSES + n] : 0.f;
    __nv_bfloat16 h = __float2bfloat16(v);
    float r = v - __bfloat162float(h);
    g_w2_hi[n * 512 + k] = h;
    g_w2_lo[n * 512 + k] = __float2bfloat16(r);
}

// ---------------- tensor-core GEMM with pre-split bf16 inputs ----------------
// MODE 0: C = acc + bias      -> split -> (Chi, Clo) bf16
// MODE 1: C = acc * scale[r]  -> fp16 z16
// MODE 2: C = acc * scale[r]  -> fp32, row stride 40, cols < 40 only
#define STG_U32 6144          // u32 per stage: (2 parts A + 2 parts B) * 128 * 12
#define SMEM_BYTES (3 * STG_U32 * 4)

template <int MODE>
__global__ __launch_bounds__(256, 2) void k_gemm_tc(
        const __nv_bfloat16* __restrict__ Ahi, const __nv_bfloat16* __restrict__ Alo,
        const __nv_bfloat16* __restrict__ Bhi, const __nv_bfloat16* __restrict__ Blo,
        const float* __restrict__ bias, const float* __restrict__ row_scale,
        __nv_bfloat16* __restrict__ Chi, __nv_bfloat16* __restrict__ Clo,
        __half* __restrict__ C16, float* __restrict__ C32, int M) {
    extern __shared__ uint32_t sm[];
    uint32_t sbase = (uint32_t)__cvta_generic_to_shared(sm);

    int tid  = threadIdx.x;
    int lane = tid & 31;
    int warp = tid >> 5;
    int wm = (warp & 3) * 32;
    int wn = (warp >> 2) * 64;
    int row0 = blockIdx.y * 128;
    int col0 = blockIdx.x * 128;

    float acc[2][8][4];
    #pragma unroll
    for (int i = 0; i < 2; i++)
        #pragma unroll
        for (int j = 0; j < 8; j++)
            #pragma unroll
            for (int k = 0; k < 4; k++) acc[i][j][k] = 0.f;

    const int r_ld  = tid >> 1;        // 0..127 (row for A, n for B)
    const int half  = tid & 1;
    const bool a_ok = (row0 + r_ld) < M;
    const size_t a_off = (size_t)(row0 + r_ld) * D + half * 8;
    const size_t b_off = (size_t)(col0 + r_ld) * D + half * 8;
    const uint32_t dst_base = (r_ld * 12 + half * 4) * 4;   // bytes within a part

    // issue stage s covering k0 = s_k*16
    auto issue = [&](int st, int ks) {
        int k0 = ks * 16;
        uint32_t sb = sbase + st * (STG_U32 * 4);
        cp16(sb + dst_base,               (const char*)(Ahi + a_off) + k0 * 2, a_ok);
        cp16(sb + 1536 * 4 + dst_base,    (const char*)(Alo + a_off) + k0 * 2, a_ok);
        cp16(sb + 3072 * 4 + dst_base,    (const char*)(Bhi + b_off) + k0 * 2, true);
        cp16(sb + 4608 * 4 + dst_base,    (const char*)(Blo + b_off) + k0 * 2, true);
        cp_commit();
    };

    issue(0, 0);
    issue(1, 1);

    const int NK = D / 16;   // 32
    const int kp = lane & 3;
    const int fr = lane >> 2;

    for (int ks = 0; ks < NK; ks++) {
        if (ks < NK - 1) cp_wait<1>(); else cp_wait<0>();
        __syncthreads();
        if (ks + 2 < NK) issue((ks + 2) % 3, ks + 2);

        const uint32_t* pAh = sm + (ks % 3) * STG_U32;
        const uint32_t* pAl = pAh + 1536;
        const uint32_t* pBh = sm + (ks % 3) * STG_U32 + 3072;
        const uint32_t* pBl = pBh + 1536;

        #pragma unroll
        for (int mt = 0; mt < 2; mt++) {
            int r = wm + mt * 16 + fr;
            uint32_t ah0 = pAh[r * 12 + kp];
            uint32_t ah1 = pAh[(r + 8) * 12 + kp];
            uint32_t ah2 = pAh[r * 12 + kp + 4];
            uint32_t ah3 = pAh[(r + 8) * 12 + kp + 4];
            uint32_t al0 = pAl[r * 12 + kp];
            uint32_t al1 = pAl[(r + 8) * 12 + kp];
            uint32_t al2 = pAl[r * 12 + kp + 4];
            uint32_t al3 = pAl[(r + 8) * 12 + kp + 4];
            #pragma unroll
            for (int nt = 0; nt < 8; nt++) {
                int n = wn + nt * 8 + fr;
                uint32_t bh0 = pBh[n * 12 + kp];
                uint32_t bh1 = pBh[n * 12 + kp + 4];
                uint32_t bl0 = pBl[n * 12 + kp];
                uint32_t bl1 = pBl[n * 12 + kp + 4];
                MMA_BF16(acc[mt][nt], ah0, ah1, ah2, ah3, bh0, bh1);
                MMA_BF16(acc[mt][nt], ah0, ah1, ah2, ah3, bl0, bl1);
                MMA_BF16(acc[mt][nt], al0, al1, al2, al3, bh0, bh1);
            }
        }
        __syncthreads();
    }

    // epilogue
    int fc = (lane & 3) * 2;
    #pragma unroll
    for (int mt = 0; mt < 2; mt++) {
        int r = row0 + wm + mt * 16 + fr;
        float s0 = 1.f, s1 = 1.f;
        if (MODE != 0) {
            if (r < M)     s0 = row_scale[r];
            if (r + 8 < M) s1 = row_scale[r + 8];
        }
        #pragma unroll
        for (int nt = 0; nt < 8; nt++) {
            int cb = col0 + wn + nt * 8 + fc;
            float v0 = acc[mt][nt][0], v1 = acc[mt][nt][1];
            float v2 = acc[mt][nt][2], v3 = acc[mt][nt][3];
            if (MODE == 0) {
                float bb0 = bias[cb], bb1 = bias[cb + 1];
                v0 += bb0; v1 += bb1; v2 += bb0; v3 += bb1;
                uint32_t h01, l01, h23, l23;
                split2(v0, v1, h01, l01);
                split2(v2, v3, h23, l23);
                if (r < M) {
                    *(uint32_t*)(Chi + (size_t)r * D + cb) = h01;
                    *(uint32_t*)(Clo + (size_t)r * D + cb) = l01;
                }
                if (r + 8 < M) {
                    *(uint32_t*)(Chi + (size_t)(r + 8) * D + cb) = h23;
                    *(uint32_t*)(Clo + (size_t)(r + 8) * D + cb) = l23;
                }
            } else if (MODE == 1) {
                if (r < M)
                    *(__half2*)(C16 + (size_t)r * D + cb) = __floats2half2_rn(v0 * s0, v1 * s0);
                if (r + 8 < M)
                    *(__half2*)(C16 + (size_t)(r + 8) * D + cb) = __floats2half2_rn(v2 * s1, v3 * s1);
            } else {
                if (cb < N_CLASSES) {
                    if (r < M)
                        *(float2*)(C32 + (size_t)r * N_CLASSES + cb) = make_float2(v0 * s0, v1 * s0);
                    if (r + 8 < M)
                        *(float2*)(C32 + (size_t)(r + 8) * N_CLASSES + cb) = make_float2(v2 * s1, v3 * s1);
                }
            }
        }
    }
}

// ---------------- SpMM: fp16 gather, writes bf16 hi/lo ----------------
// out[v,c] = relu( norm_dst[v] * sum_u z16[u,c] + bias[c] ),  256-col chunk
__global__ __launch_bounds__(128) void k_spmm16(const __half* __restrict__ z,
                                                const float* __restrict__ bias,
                                                __nv_bfloat16* __restrict__ Ohi,
                                                __nv_bfloat16* __restrict__ Olo,
                                                int chunk) {
    int v = blockIdx.x * 4 + (threadIdx.x >> 5);
    if (v >= N_NODES) return;
    int lane = threadIdx.x & 31;
    int coff = chunk * 256 + lane * 8;

    int beg = g_rowptr[v], end = g_rowptr[v + 1];
    float acc[8];
    #pragma unroll
    for (int j = 0; j < 8; j++) acc[j] = 0.f;

    int e = beg;
    for (; e + 1 < end; e += 2) {
        int u0 = g_csr_src[e];
        int u1 = g_csr_src[e + 1];
        uint4 q0 = *(const uint4*)(z + (size_t)u0 * D + coff);
        uint4 q1 = *(const uint4*)(z + (size_t)u1 * D + coff);
        const __half2* p0 = (const __half2*)&q0;
        const __half2* p1 = (const __half2*)&q1;
        #pragma unroll
        for (int p = 0; p < 4; p++) {
            float2 f0 = __half22float2(p0[p]);
            float2 f1 = __half22float2(p1[p]);
            acc[2 * p]     += f0.x + f1.x;
            acc[2 * p + 1] += f0.y + f1.y;
        }
    }
    if (e < end) {
        int u0 = g_csr_src[e];
        uint4 q0 = *(const uint4*)(z + (size_t)u0 * D + coff);
        const __half2* p0 = (const __half2*)&q0;
        #pragma unroll
        for (int p = 0; p < 4; p++) {
            float2 f0 = __half22float2(p0[p]);
            acc[2 * p]     += f0.x;
            acc[2 * p + 1] += f0.y;
        }
    }

    float nd = g_norm_dst[v];
    float4 b0 = *(const float4*)(bias + coff);
    float4 b1 = *(const float4*)(bias + coff + 4);
    float bb[8] = { b0.x, b0.y, b0.z, b0.w, b1.x, b1.y, b1.z, b1.w };
    uint32_t oh[4], ol[4];
    #pragma unroll
    for (int p = 0; p < 4; p++) {
        float x = fmaxf(fmaf(acc[2 * p], nd, bb[2 * p]), 0.f);
        float y = fmaxf(fmaf(acc[2 * p + 1], nd, bb[2 * p + 1]), 0.f);
        split2(x, y, oh[p], ol[p]);
    }
    *(uint4*)(Ohi + (size_t)v * D + coff) = make_uint4(oh[0], oh[1], oh[2], oh[3]);
    *(uint4*)(Olo + (size_t)v * D + coff) = make_uint4(ol[0], ol[1], ol[2], ol[3]);
}

// ---------------- final SpMM on 40-wide z40 (L2-resident) ----------------
__global__ __launch_bounds__(256) void k_spmm40(const float* __restrict__ z40,
                                                const float* __restrict__ bias,
                                                float* __restrict__ out) {
    int v = blockIdx.x * 8 + (threadIdx.x >> 5);
    if (v >= N_NODES) return;
    int lane = threadIdx.x & 31;
    if (lane >= 20) return;
    int c = lane * 2;

    int beg = g_rowptr[v], end = g_rowptr[v + 1];
    float2 acc0 = make_float2(0.f, 0.f);
    float2 acc1 = make_float2(0.f, 0.f);
    int e = beg;
    for (; e + 1 < end; e += 2) {
        int u0 = g_csr_src[e];
        int u1 = g_csr_src[e + 1];
        float2 x0 = *(const float2*)(z40 + (size_t)u0 * N_CLASSES + c);
        float2 x1 = *(const float2*)(z40 + (size_t)u1 * N_CLASSES + c);
        acc0.x += x0.x; acc0.y += x0.y;
        acc1.x += x1.x; acc1.y += x1.y;
    }
    if (e < end) {
        int u0 = g_csr_src[e];
        float2 x0 = *(const float2*)(z40 + (size_t)u0 * N_CLASSES + c);
        acc0.x += x0.x; acc0.y += x0.y;
    }
    float nd = g_norm_dst[v];
    float2 o;
    o.x = fmaf(acc0.x + acc1.x, nd, bias[c]);
    o.y = fmaf(acc0.y + acc1.y, nd, bias[c + 1]);
    *(float2*)(out + (size_t)v * N_CLASSES + c) = o;
}

// ---------------- launch ----------------
extern "C" void kernel_launch(void* const* d_in, const int* in_sizes, int n_in,
                              void* d_out, int out_size) {
    const float* features = (const float*)d_in[0];
    const int*   src      = (const int*)d_in[1];
    const int*   dst      = (const int*)d_in[2];
    const float* W_lin    = (const float*)d_in[3];
    const float* b_lin    = (const float*)d_in[4];
    const float* W0       = (const float*)d_in[5];
    const float* b0       = (const float*)d_in[6];
    const float* W1       = (const float*)d_in[7];
    const float* b1       = (const float*)d_in[8];
    const float* W2       = (const float*)d_in[9];
    const float* b2       = (const float*)d_in[10];
    float* out = (float*)d_out;

    static bool attr_done = false;
    cudaFuncSetAttribute(k_gemm_tc<0>, cudaFuncAttributeMaxDynamicSharedMemorySize, SMEM_BYTES);
    cudaFuncSetAttribute(k_gemm_tc<1>, cudaFuncAttributeMaxDynamicSharedMemorySize, SMEM_BYTES);
    cudaFuncSetAttribute(k_gemm_tc<2>, cudaFuncAttributeMaxDynamicSharedMemorySize, SMEM_BYTES);
    (void)attr_done;

    // device pointers to globals
    __nv_bfloat16 *fhi, *flo, *hhi, *hlo;
    __nv_bfloat16 *wl_hi, *wl_lo, *w0_hi, *w0_lo, *w1_hi, *w1_lo, *w2_hi, *w2_lo;
    __half* z16; float *z40, *ns;
    cudaGetSymbolAddress((void**)&fhi, g_fhi);
    cudaGetSymbolAddress((void**)&flo, g_flo);
    cudaGetSymbolAddress((void**)&hhi, g_hhi);
    cudaGetSymbolAddress((void**)&hlo, g_hlo);
    cudaGetSymbolAddress((void**)&wl_hi, g_wl_hi);
    cudaGetSymbolAddress((void**)&wl_lo, g_wl_lo);
    cudaGetSymbolAddress((void**)&w0_hi, g_w0_hi);
    cudaGetSymbolAddress((void**)&w0_lo, g_w0_lo);
    cudaGetSymbolAddress((void**)&w1_hi, g_w1_hi);
    cudaGetSymbolAddress((void**)&w1_lo, g_w1_lo);
    cudaGetSymbolAddress((void**)&w2_hi, g_w2_hi);
    cudaGetSymbolAddress((void**)&w2_lo, g_w2_lo);
    cudaGetSymbolAddress((void**)&z16, g_z16);
    cudaGetSymbolAddress((void**)&z40, g_z40);
    cudaGetSymbolAddress((void**)&ns, g_norm_src);

    const int NB_N = (N_NODES + 255) / 256;
    const int NB_E = (N_EDGES + 255) / 256;

    // graph build
    k_zero_ints<<<NB_N, 256>>>();
    k_degrees<<<NB_E, 256>>>(src, dst);
    k_norms<<<NB_N, 256>>>();
    k_scan1<<<NSCAN_BLK, 1024>>>();
    k_scan2<<<1, 128>>>();
    k_scan3<<<NSCAN_BLK, 1024>>>();
    k_scatter<<<NB_E, 256>>>(src, dst);

    // splits
    k_split_feat<<<(int)(((size_t)N_NODES * D / 8) / 256), 256>>>(features);
    k_split_w<<<1024, 256>>>(W_lin, wl_hi, wl_lo);
    k_split_w<<<1024, 256>>>(W0, w0_hi, w0_lo);
    k_split_w<<<1024, 256>>>(W1, w1_hi, w1_lo);
    k_split_w2<<<256, 256>>>(W2);

    dim3 ggrid(4, (N_NODES + 127) / 128);
    dim3 ggrid40(1, (N_NODES + 127) / 128);
    const int spmm_blocks = (N_NODES + 3) / 4;

    // h = features @ W_lin + b_lin   (MODE 0 -> h hi/lo)
    k_gemm_tc<0><<<ggrid, 256, SMEM_BYTES>>>(fhi, flo, wl_hi, wl_lo, b_lin, nullptr,
                                             hhi, hlo, nullptr, nullptr, N_NODES);
    // layer 0: z16 = (h @ W0) * norm_src ; h' = relu(S z16 * norm_dst + b0) -> f buffers
    k_gemm_tc<1><<<ggrid, 256, SMEM_BYTES>>>(hhi, hlo, w0_hi, w0_lo, nullptr, ns,
                                             nullptr, nullptr, z16, nullptr, N_NODES);
    k_spmm16<<<spmm_blocks, 128>>>(z16, b0, fhi, flo, 0);
    k_spmm16<<<spmm_blocks, 128>>>(z16, b0, fhi, flo, 1);
    // layer 1
    k_gemm_tc<1><<<ggrid, 256, SMEM_BYTES>>>(fhi, flo, w1_hi, w1_lo, nullptr, ns,
                                             nullptr, nullptr, z16, nullptr, N_NODES);
    k_spmm16<<<spmm_blocks, 128>>>(z16, b1, hhi, hlo, 0);
    k_spmm16<<<spmm_blocks, 128>>>(z16, b1, hhi, hlo, 1);
    // layer 2: z40 = (h @ W2) * norm_src ; out = S z40 * norm_dst + b2
    k_gemm_tc<2><<<ggrid40, 256, SMEM_BYTES>>>(hhi, hlo, w2_hi, w2_lo, nullptr, ns,
                                               nullptr, nullptr, nullptr, z40, N_NODES);
    k_spmm40<<<(N_NODES + 7) / 8, 256>>>(z40, b2, out);
}

// round 5
// speedup vs baseline: 3.1482x; 1.1658x over previous
#include <cuda_runtime.h>
#include <cuda_bf16.h>
#include <cuda_fp16.h>
#include <math.h>
#include <stdint.h>

#define N_NODES   100000
#define N_EDGES   3200000
#define D         512
#define N_CLASSES 40
#define NSCAN_BLK 98

// ---------------- scratch (device globals; no allocs allowed) ----------------
__device__ float g_bufA[(size_t)N_NODES * D];   // node features (tf32-truncated fp32)
__device__ float g_bufB[(size_t)N_NODES * D];
__device__ __half g_z16[(size_t)N_NODES * D];   // GEMM out / SpMM in
__device__ float g_z40[(size_t)N_NODES * N_CLASSES];
__device__ float g_wl[D * D];                    // W_lin^T (tf32-trunc fp32)
__device__ float g_w0[D * D];
__device__ float g_w1[D * D];
__device__ float g_w2[128 * D];                  // W2^T padded to 128 rows
__device__ int   g_indeg[N_NODES];
__device__ int   g_outdeg[N_NODES];
__device__ float g_norm_src[N_NODES];
__device__ float g_norm_dst[N_NODES];
__device__ int   g_rowptr[N_NODES + 1];
__device__ int   g_rowctr[N_NODES];
__device__ int   g_csr_src[N_EDGES];
__device__ int   g_blksum[NSCAN_BLK];
__device__ int   g_blkoff[NSCAN_BLK];

// ---------------- helpers ----------------
__device__ __forceinline__ float tf32r(float x) {
    uint32_t y;
    asm("cvt.rna.tf32.f32 %0, %1;" : "=r"(y) : "f"(x));
    return __uint_as_float(y);
}

__device__ __forceinline__ void cp16(uint32_t dst_smem, const void* src, bool valid) {
    asm volatile("cp.async.cg.shared.global [%0], [%1], 16, %2;"
                 :: "r"(dst_smem), "l"(src), "r"(valid ? 16 : 0));
}
__device__ __forceinline__ void cp_commit() {
    asm volatile("cp.async.commit_group;");
}
template <int N>
__device__ __forceinline__ void cp_wait() {
    asm volatile("cp.async.wait_group %0;" :: "n"(N));
}

#define MMA_TF32(c, a0, a1, a2, a3, b0, b1)                                    \
    asm volatile("mma.sync.aligned.m16n8k8.row.col.f32.tf32.tf32.f32 "         \
                 "{%0,%1,%2,%3}, {%4,%5,%6,%7}, {%8,%9}, {%0,%1,%2,%3};"       \
                 : "+f"(c[0]), "+f"(c[1]), "+f"(c[2]), "+f"(c[3])              \
                 : "r"(a0), "r"(a1), "r"(a2), "r"(a3), "r"(b0), "r"(b1))

// ---------------- truncation / transpose passes ----------------
__global__ void k_trunc_feat(const float* __restrict__ f) {
    size_t i = ((size_t)blockIdx.x * blockDim.x + threadIdx.x) * 4;
    float4 a = *(const float4*)(f + i);
    a.x = tf32r(a.x); a.y = tf32r(a.y); a.z = tf32r(a.z); a.w = tf32r(a.w);
    *(float4*)(g_bufA + i) = a;
}

// W [k][n] fp32 -> W^T [n][k] tf32-trunc fp32
__global__ void k_trunc_w(const float* __restrict__ W, float* __restrict__ Wt) {
    int idx = blockIdx.x * blockDim.x + threadIdx.x;   // 512*512
    int k = idx >> 9, n = idx & 511;
    Wt[n * 512 + k] = tf32r(W[k * 512 + n]);
}

// W2 [k][40] -> padded [128][512]
__global__ void k_trunc_w2(const float* __restrict__ W2) {
    int idx = blockIdx.x * blockDim.x + threadIdx.x;   // 128*512
    int n = idx >> 9, k = idx & 511;
    float v = (n < N_CLASSES) ? W2[k * N_CLASSES + n] : 0.f;
    g_w2[n * 512 + k] = tf32r(v);
}

// ---------------- graph preprocessing ----------------
__global__ void k_zero_ints() {
    int i = blockIdx.x * blockDim.x + threadIdx.x;
    if (i < N_NODES) { g_indeg[i] = 0; g_outdeg[i] = 0; g_rowctr[i] = 0; }
}

__global__ void k_degrees(const int* __restrict__ src, const int* __restrict__ dst) {
    int e = blockIdx.x * blockDim.x + threadIdx.x;
    if (e < N_EDGES) {
        atomicAdd(&g_outdeg[src[e]], 1);
        atomicAdd(&g_indeg[dst[e]], 1);
    }
}

__global__ void k_norms() {
    int i = blockIdx.x * blockDim.x + threadIdx.x;
    if (i < N_NODES) {
        g_norm_src[i] = rsqrtf(fmaxf((float)g_outdeg[i], 1.0f));
        g_norm_dst[i] = rsqrtf(fmaxf((float)g_indeg[i], 1.0f));
    }
}

__global__ void k_scan1() {
    __shared__ int ws[32];
    int tid = threadIdx.x, lane = tid & 31, w = tid >> 5;
    int i = blockIdx.x * 1024 + tid;
    int v = (i < N_NODES) ? g_indeg[i] : 0;
    int x = v;
    #pragma unroll
    for (int o = 1; o < 32; o <<= 1) {
        int y = __shfl_up_sync(0xFFFFFFFFu, x, o);
        if (lane >= o) x += y;
    }
    if (lane == 31) ws[w] = x;
    __syncthreads();
    if (w == 0) {
        int y = ws[lane];
        #pragma unroll
        for (int o = 1; o < 32; o <<= 1) {
            int z = __shfl_up_sync(0xFFFFFFFFu, y, o);
            if (lane >= o) y += z;
        }
        ws[lane] = y;
    }
    __syncthreads();
    int incl = x + (w > 0 ? ws[w - 1] : 0);
    if (i < N_NODES) g_rowptr[i + 1] = incl;
    if (tid == 1023) g_blksum[blockIdx.x] = incl;
}

__global__ void k_scan2() {
    __shared__ int ws[4];
    int tid = threadIdx.x, lane = tid & 31, w = tid >> 5;
    int v = (tid < NSCAN_BLK) ? g_blksum[tid] : 0;
    int x = v;
    #pragma unroll
    for (int o = 1; o < 32; o <<= 1) {
        int y = __shfl_up_sync(0xFFFFFFFFu, x, o);
        if (lane >= o) x += y;
    }
    if (lane == 31) ws[w] = x;
    __syncthreads();
    if (tid == 0) {
        int s = 0;
        #pragma unroll
        for (int j = 0; j < 4; j++) { int t = ws[j]; ws[j] = s; s += t; }
    }
    __syncthreads();
    int excl = x - v + ws[w];
    if (tid < NSCAN_BLK) g_blkoff[tid] = excl;
}

__global__ void k_scan3() {
    int i = blockIdx.x * 1024 + threadIdx.x;
    if (i < N_NODES) g_rowptr[i + 1] += g_blkoff[blockIdx.x];
    if (i == 0) g_rowptr[0] = 0;
}

__global__ void k_scatter(const int* __restrict__ src, const int* __restrict__ dst) {
    int e = blockIdx.x * blockDim.x + threadIdx.x;
    if (e < N_EDGES) {
        int d = dst[e];
        int pos = g_rowptr[d] + atomicAdd(&g_rowctr[d], 1);
        g_csr_src[pos] = src[e];
    }
}

// ---------------- tensor-core GEMM (single-pass tf32) ----------------
// MODE 0: C = acc + bias      -> tf32-trunc fp32 Cf
// MODE 1: C = acc * scale[r]  -> fp16 C16
// MODE 2: C = acc * scale[r]  -> fp32 C32, row stride 40, cols < 40 only
#define ROWS_U32 20                       // padded row stride (conflict-free)
#define PART_U32 (128 * ROWS_U32)         // 2560
#define STG_U32  (2 * PART_U32)           // A + B = 5120
#define SMEM_BYTES (3 * STG_U32 * 4)      // 61440

template <int MODE>
__global__ __launch_bounds__(256, 2) void k_gemm_tc(
        const float* __restrict__ A, const float* __restrict__ B,
        const float* __restrict__ bias, const float* __restrict__ row_scale,
        float* __restrict__ Cf, __half* __restrict__ C16,
        float* __restrict__ C32, int M) {
    extern __shared__ uint32_t sm[];
    uint32_t sbase = (uint32_t)__cvta_generic_to_shared(sm);

    int tid  = threadIdx.x;
    int lane = tid & 31;
    int warp = tid >> 5;
    int wm = (warp & 3) * 32;
    int wn = (warp >> 2) * 64;
    int row0 = blockIdx.y * 128;
    int col0 = blockIdx.x * 128;

    float acc[2][8][4];
    #pragma unroll
    for (int i = 0; i < 2; i++)
        #pragma unroll
        for (int j = 0; j < 8; j++)
            #pragma unroll
            for (int k = 0; k < 4; k++) acc[i][j][k] = 0.f;

    const int r_ld = tid >> 1;         // 0..127
    const int half = tid & 1;
    const bool a_ok = (row0 + r_ld) < M;
    const size_t a_off = (size_t)(row0 + r_ld) * D + half * 8;   // 8 floats = 32B
    const size_t b_off = (size_t)(col0 + r_ld) * D + half * 8;
    const uint32_t dst_base = (r_ld * ROWS_U32 + half * 8) * 4;  // bytes

    auto issue = [&](int st, int ks) {
        int k0 = ks * 16;
        uint32_t sb = sbase + st * (STG_U32 * 4);
        const char* pa = (const char*)(A + a_off + k0);
        const char* pb = (const char*)(B + b_off + k0);
        cp16(sb + dst_base,                   pa,      a_ok);
        cp16(sb + dst_base + 16,              pa + 16, a_ok);
        cp16(sb + PART_U32 * 4 + dst_base,      pb,      true);
        cp16(sb + PART_U32 * 4 + dst_base + 16, pb + 16, true);
        cp_commit();
    };

    issue(0, 0);
    issue(1, 1);

    const int NK = D / 16;   // 32
    const int kp = lane & 3;
    const int fr = lane >> 2;

    for (int ks = 0; ks < NK; ks++) {
        if (ks < NK - 1) cp_wait<1>(); else cp_wait<0>();
        __syncthreads();
        if (ks + 2 < NK) issue((ks + 2) % 3, ks + 2);

        const uint32_t* pA = sm + (ks % 3) * STG_U32;
        const uint32_t* pB = pA + PART_U32;

        #pragma unroll
        for (int mt = 0; mt < 2; mt++) {
            int r = wm + mt * 16 + fr;
            const uint32_t* r0p = pA + r * ROWS_U32;
            const uint32_t* r8p = pA + (r + 8) * ROWS_U32;
            uint32_t a0 = r0p[kp],     a1 = r8p[kp];
            uint32_t a2 = r0p[kp + 4], a3 = r8p[kp + 4];
            uint32_t a4 = r0p[kp + 8], a5 = r8p[kp + 8];
            uint32_t a6 = r0p[kp + 12], a7 = r8p[kp + 12];
            #pragma unroll
            for (int nt = 0; nt < 8; nt++) {
                const uint32_t* np = pB + (wn + nt * 8 + fr) * ROWS_U32;
                uint32_t b0 = np[kp], b1 = np[kp + 4];
                uint32_t b2 = np[kp + 8], b3 = np[kp + 12];
                MMA_TF32(acc[mt][nt], a0, a1, a2, a3, b0, b1);
                MMA_TF32(acc[mt][nt], a4, a5, a6, a7, b2, b3);
            }
        }
        __syncthreads();
    }

    // epilogue
    int fc = (lane & 3) * 2;
    #pragma unroll
    for (int mt = 0; mt < 2; mt++) {
        int r = row0 + wm + mt * 16 + fr;
        float s0 = 1.f, s1 = 1.f;
        if (MODE != 0) {
            if (r < M)     s0 = row_scale[r];
            if (r + 8 < M) s1 = row_scale[r + 8];
        }
        #pragma unroll
        for (int nt = 0; nt < 8; nt++) {
            int cb = col0 + wn + nt * 8 + fc;
            float v0 = acc[mt][nt][0], v1 = acc[mt][nt][1];
            float v2 = acc[mt][nt][2], v3 = acc[mt][nt][3];
            if (MODE == 0) {
                float bb0 = bias[cb], bb1 = bias[cb + 1];
                v0 = tf32r(v0 + bb0); v1 = tf32r(v1 + bb1);
                v2 = tf32r(v2 + bb0); v3 = tf32r(v3 + bb1);
                if (r < M)     *(float2*)(Cf + (size_t)r * D + cb)       = make_float2(v0, v1);
                if (r + 8 < M) *(float2*)(Cf + (size_t)(r + 8) * D + cb) = make_float2(v2, v3);
            } else if (MODE == 1) {
                if (r < M)
                    *(__half2*)(C16 + (size_t)r * D + cb) = __floats2half2_rn(v0 * s0, v1 * s0);
                if (r + 8 < M)
                    *(__half2*)(C16 + (size_t)(r + 8) * D + cb) = __floats2half2_rn(v2 * s1, v3 * s1);
            } else {
                if (cb < N_CLASSES) {
                    if (r < M)
                        *(float2*)(C32 + (size_t)r * N_CLASSES + cb) = make_float2(v0 * s0, v1 * s0);
                    if (r + 8 < M)
                        *(float2*)(C32 + (size_t)(r + 8) * N_CLASSES + cb) = make_float2(v2 * s1, v3 * s1);
                }
            }
        }
    }
}

// ---------------- SpMM: fp16 gather, writes tf32-trunc fp32 ----------------
// out[v,c] = relu( norm_dst[v] * sum_u z16[u,c] + bias[c] ),  256-col chunk
__global__ __launch_bounds__(128) void k_spmm16(const __half* __restrict__ z,
                                                const float* __restrict__ bias,
                                                float* __restrict__ O,
                                                int chunk) {
    int v = blockIdx.x * 4 + (threadIdx.x >> 5);
    if (v >= N_NODES) return;
    int lane = threadIdx.x & 31;
    int coff = chunk * 256 + lane * 8;

    int beg = g_rowptr[v], end = g_rowptr[v + 1];
    float acc[8];
    #pragma unroll
    for (int j = 0; j < 8; j++) acc[j] = 0.f;

    int e = beg;
    for (; e + 3 < end; e += 4) {
        int u0 = g_csr_src[e];
        int u1 = g_csr_src[e + 1];
        int u2 = g_csr_src[e + 2];
        int u3 = g_csr_src[e + 3];
        uint4 q0 = *(const uint4*)(z + (size_t)u0 * D + coff);
        uint4 q1 = *(const uint4*)(z + (size_t)u1 * D + coff);
        uint4 q2 = *(const uint4*)(z + (size_t)u2 * D + coff);
        uint4 q3 = *(const uint4*)(z + (size_t)u3 * D + coff);
        const __half2* p0 = (const __half2*)&q0;
        const __half2* p1 = (const __half2*)&q1;
        const __half2* p2 = (const __half2*)&q2;
        const __half2* p3 = (const __half2*)&q3;
        #pragma unroll
        for (int p = 0; p < 4; p++) {
            float2 f0 = __half22float2(p0[p]);
            float2 f1 = __half22float2(p1[p]);
            float2 f2 = __half22float2(p2[p]);
            float2 f3 = __half22float2(p3[p]);
            acc[2 * p]     += (f0.x + f1.x) + (f2.x + f3.x);
            acc[2 * p + 1] += (f0.y + f1.y) + (f2.y + f3.y);
        }
    }
    for (; e < end; e++) {
        int u0 = g_csr_src[e];
        uint4 q0 = *(const uint4*)(z + (size_t)u0 * D + coff);
        const __half2* p0 = (const __half2*)&q0;
        #pragma unroll
        for (int p = 0; p < 4; p++) {
            float2 f0 = __half22float2(p0[p]);
            acc[2 * p]     += f0.x;
            acc[2 * p + 1] += f0.y;
        }
    }

    float nd = g_norm_dst[v];
    float4 b0 = *(const float4*)(bias + coff);
    float4 b1 = *(const float4*)(bias + coff + 4);
    float bb[8] = { b0.x, b0.y, b0.z, b0.w, b1.x, b1.y, b1.z, b1.w };
    float o[8];
    #pragma unroll
    for (int j = 0; j < 8; j++)
        o[j] = tf32r(fmaxf(fmaf(acc[j], nd, bb[j]), 0.f));
    *(float4*)(O + (size_t)v * D + coff)     = make_float4(o[0], o[1], o[2], o[3]);
    *(float4*)(O + (size_t)v * D + coff + 4) = make_float4(o[4], o[5], o[6], o[7]);
}

// ---------------- final SpMM on 40-wide z40 (L2-resident) ----------------
__global__ __launch_bounds__(256) void k_spmm40(const float* __restrict__ z40,
                                                const float* __restrict__ bias,
                                                float* __restrict__ out) {
    int v = blockIdx.x * 8 + (threadIdx.x >> 5);
    if (v >= N_NODES) return;
    int lane = threadIdx.x & 31;
    if (lane >= 20) return;
    int c = lane * 2;

    int beg = g_rowptr[v], end = g_rowptr[v + 1];
    float2 acc0 = make_float2(0.f, 0.f);
    float2 acc1 = make_float2(0.f, 0.f);
    int e = beg;
    for (; e + 1 < end; e += 2) {
        int u0 = g_csr_src[e];
        int u1 = g_csr_src[e + 1];
        float2 x0 = *(const float2*)(z40 + (size_t)u0 * N_CLASSES + c);
        float2 x1 = *(const float2*)(z40 + (size_t)u1 * N_CLASSES + c);
        acc0.x += x0.x; acc0.y += x0.y;
        acc1.x += x1.x; acc1.y += x1.y;
    }
    if (e < end) {
        int u0 = g_csr_src[e];
        float2 x0 = *(const float2*)(z40 + (size_t)u0 * N_CLASSES + c);
        acc0.x += x0.x; acc0.y += x0.y;
    }
    float nd = g_norm_dst[v];
    float2 o;
    o.x = fmaf(acc0.x + acc1.x, nd, bias[c]);
    o.y = fmaf(acc0.y + acc1.y, nd, bias[c + 1]);
    *(float2*)(out + (size_t)v * N_CLASSES + c) = o;
}

// ---------------- launch ----------------
extern "C" void kernel_launch(void* const* d_in, const int* in_sizes, int n_in,
                              void* d_out, int out_size) {
    const float* features = (const float*)d_in[0];
    const int*   src      = (const int*)d_in[1];
    const int*   dst      = (const int*)d_in[2];
    const float* W_lin    = (const float*)d_in[3];
    const float* b_lin    = (const float*)d_in[4];
    const float* W0       = (const float*)d_in[5];
    const float* b0       = (const float*)d_in[6];
    const float* W1       = (const float*)d_in[7];
    const float* b1       = (const float*)d_in[8];
    const float* W2       = (const float*)d_in[9];
    const float* b2       = (const float*)d_in[10];
    float* out = (float*)d_out;

    cudaFuncSetAttribute(k_gemm_tc<0>, cudaFuncAttributeMaxDynamicSharedMemorySize, SMEM_BYTES);
    cudaFuncSetAttribute(k_gemm_tc<1>, cudaFuncAttributeMaxDynamicSharedMemorySize, SMEM_BYTES);
    cudaFuncSetAttribute(k_gemm_tc<2>, cudaFuncAttributeMaxDynamicSharedMemorySize, SMEM_BYTES);

    float *bufA, *bufB, *wl, *w0, *w1, *w2, *z40, *ns;
    __half* z16;
    cudaGetSymbolAddress((void**)&bufA, g_bufA);
    cudaGetSymbolAddress((void**)&bufB, g_bufB);
    cudaGetSymbolAddress((void**)&wl, g_wl);
    cudaGetSymbolAddress((void**)&w0, g_w0);
    cudaGetSymbolAddress((void**)&w1, g_w1);
    cudaGetSymbolAddress((void**)&w2, g_w2);
    cudaGetSymbolAddress((void**)&z16, g_z16);
    cudaGetSymbolAddress((void**)&z40, g_z40);
    cudaGetSymbolAddress((void**)&ns, g_norm_src);

    const int NB_N = (N_NODES + 255) / 256;
    const int NB_E = (N_EDGES + 255) / 256;

    dim3 ggrid(4, (N_NODES + 127) / 128);
    dim3 ggrid40(1, (N_NODES + 127) / 128);
    const int spmm_blocks = (N_NODES + 3) / 4;

    // --- splits first so GEMM0 is launch #5 (ncu -s 5 profiles it) ---
    k_trunc_feat<<<(int)(((size_t)N_NODES * D / 4) / 256), 256>>>(features);   // 0
    k_trunc_w<<<1024, 256>>>(W_lin, wl);                                       // 1
    k_trunc_w<<<1024, 256>>>(W0, w0);                                          // 2
    k_trunc_w<<<1024, 256>>>(W1, w1);                                          // 3
    k_trunc_w2<<<256, 256>>>(W2);                                              // 4

    // h = features @ W_lin + b_lin   (MODE 0 -> bufB)
    k_gemm_tc<0><<<ggrid, 256, SMEM_BYTES>>>(bufA, wl, b_lin, nullptr,         // 5  <- profiled
                                             bufB, nullptr, nullptr, N_NODES);

    // --- graph build ---
    k_zero_ints<<<NB_N, 256>>>();
    k_degrees<<<NB_E, 256>>>(src, dst);
    k_norms<<<NB_N, 256>>>();
    k_scan1<<<NSCAN_BLK, 1024>>>();
    k_scan2<<<1, 128>>>();
    k_scan3<<<NSCAN_BLK, 1024>>>();
    k_scatter<<<NB_E, 256>>>(src, dst);

    // layer 0: z16 = (h @ W0) * norm_src ; h' = relu(S z16 * norm_dst + b0) -> bufA
    k_gemm_tc<1><<<ggrid, 256, SMEM_BYTES>>>(bufB, w0, nullptr, ns,
                                             nullptr, z16, nullptr, N_NODES);
    k_spmm16<<<spmm_blocks, 128>>>(z16, b0, bufA, 0);
    k_spmm16<<<spmm_blocks, 128>>>(z16, b0, bufA, 1);
    // layer 1
    k_gemm_tc<1><<<ggrid, 256, SMEM_BYTES>>>(bufA, w1, nullptr, ns,
                                             nullptr, z16, nullptr, N_NODES);
    k_spmm16<<<spmm_blocks, 128>>>(z16, b1, bufB, 0);
    k_spmm16<<<spmm_blocks, 128>>>(z16, b1, bufB, 1);
    // layer 2: z40 = (h @ W2) * norm_src ; out = S z40 * norm_dst + b2
    k_gemm_tc<2><<<ggrid40, 256, SMEM_BYTES>>>(bufB, w2, nullptr, ns,
                                               nullptr, nullptr, z40, N_NODES);
    k_spmm40<<<(N_NODES + 7) / 8, 256>>>(z40, b2, out);
}